// round 2
// baseline (speedup 1.0000x reference)
#include <cuda_runtime.h>
#include <cstdint>

// Problem constants
#define B_  64
#define H_  128
#define W_  128
#define C_  10
#define FD_ 32
#define HID_ 64

// Tile config
#define TW 32
#define TH 8
#define HW 34   // halo width  (TW+2)
#define HH 10   // halo height (TH+2)
#define NPIX  (TW*TH)   // 256
#define NHALO (HW*HH)   // 340
#define NTHREADS 512

// Shared memory layout (float offsets)
#define OFF_SY     0
#define OFF_SA     (OFF_SY + NHALO*HID_)     // 21760
#define OFF_SB     (OFF_SA + NPIX*HID_)      // 38144
#define OFF_SC     (OFF_SB + NHALO*C_)       // 41544
#define OFF_MW2T   (OFF_SC + NPIX*24)        // 47688
#define OFF_UW2T   (OFF_MW2T + 640)          // 48328
#define OFF_UW1    (OFF_UW2T + 640)          // 48968
#define OFF_WSELF  (OFF_UW1 + 1280)          // 50248
#define OFF_WNEIGH (OFF_WSELF + 640)         // 50888
#define OFF_WC     (OFF_WNEIGH + 640)        // 51528
#define OFF_UB1    (OFF_WC + 192)            // 51720
#define OFF_BASE   (OFF_UB1 + 64)            // 51784
#define OFF_MB2    (OFF_BASE + 64)           // 51848
#define OFF_UB2    (OFF_MB2 + 10)
#define OFF_GAMMA  (OFF_UB2 + 10)
#define OFF_BETA   (OFF_GAMMA + 10)
#define OFF_SOUT   (OFF_BETA + 10)           // 51888
#define SMEM_FLOATS (OFF_SOUT + NPIX*C_)     // 54448
#define SMEM_BYTES  (SMEM_FLOATS * 4)        // 217792

__global__ void __launch_bounds__(NTHREADS, 1)
cmp_kernel(const float* __restrict__ beliefs,
           const float* __restrict__ constraints,
           const float* __restrict__ fnembed,
           const float* __restrict__ mw1, const float* __restrict__ mb1,
           const float* __restrict__ mw2, const float* __restrict__ mb2,
           const float* __restrict__ uw1, const float* __restrict__ ub1,
           const float* __restrict__ uw2, const float* __restrict__ ub2,
           const float* __restrict__ gamma_, const float* __restrict__ beta_,
           float* __restrict__ out)
{
    extern __shared__ __align__(16) float sm[];
    const int tid = threadIdx.x;
    const int b  = blockIdx.z;
    const int x0 = blockIdx.x * TW;
    const int y0 = blockIdx.y * TH;

    // ---------------- Phase 0: stage weights into smem ----------------
    // mw1 row layout: rows [0,10)=W_self, [10,20)=W_neigh, [20,23)=W_con, [23,55)=W_fn
    for (int i = tid; i < 640; i += NTHREADS) {
        sm[OFF_WSELF  + i] = mw1[i];
        sm[OFF_WNEIGH + i] = mw1[640 + i];
        // transposed copies: m2t[k*64 + j] = m2[j*10 + k]
        sm[OFF_MW2T + i] = mw2[(i & 63) * 10 + (i >> 6)];
        sm[OFF_UW2T + i] = uw2[(i & 63) * 10 + (i >> 6)];
    }
    for (int i = tid; i < 192; i += NTHREADS)  sm[OFF_WC  + i] = mw1[1280 + i];
    for (int i = tid; i < 1280; i += NTHREADS) sm[OFF_UW1 + i] = uw1[i];
    if (tid < 64) {
        sm[OFF_UB1 + tid] = ub1[tid];
        // base[j] = mb1[j] + fn_b @ W_fn[:, j]
        float s = mb1[tid];
        const float* f = fnembed + b * FD_;
        #pragma unroll
        for (int k = 0; k < FD_; ++k)
            s = fmaf(f[k], mw1[(23 + k) * HID_ + tid], s);
        sm[OFF_BASE + tid] = s;
    }
    if (tid >= 64 && tid < 74) {
        int k = tid - 64;
        sm[OFF_MB2   + k] = mb2[k];
        sm[OFF_UB2   + k] = ub2[k];
        sm[OFF_GAMMA + k] = gamma_[k];
        sm[OFF_BETA  + k] = beta_[k];
    }

    // ---------------- Phase 1: beliefs halo (replicate-pad clamp) ----------------
    for (int idx = tid; idx < NHALO * C_; idx += NTHREADS) {
        int p = idx / C_, i = idx - p * C_;
        int hr = p / HW, hc = p - hr * HW;
        int gy = min(max(y0 - 1 + hr, 0), H_ - 1);
        int gx = min(max(x0 - 1 + hc, 0), W_ - 1);
        sm[OFF_SB + idx] = beliefs[((size_t)(b * H_ + gy) * W_ + gx) * C_ + i];
    }
    // ---------------- Phase 1b: constraints tile (float4, coalesced) -------------
    {
        float4* dst = (float4*)&sm[OFF_SC];
        for (int idx = tid; idx < NPIX * 6; idx += NTHREADS) {
            int r = idx / (TW * 6), o = idx - r * (TW * 6);
            const float4* src = (const float4*)(constraints +
                ((size_t)(b * H_ + y0 + r) * W_ + x0) * 24);
            dst[idx] = src[o];
        }
    }
    __syncthreads();

    // ---------------- Phase 2: y = beliefs@W_neigh over halo; a = self@W_self + base
    {
        const int j = tid & 63;   // stride 512 keeps j fixed per thread
        float wn[C_];
        #pragma unroll
        for (int i = 0; i < C_; ++i) wn[i] = sm[OFF_WNEIGH + i * HID_ + j];
        for (int idx = tid; idx < NHALO * HID_; idx += NTHREADS) {
            int p = idx >> 6;
            const float* bp = &sm[OFF_SB + p * C_];
            float s = 0.f;
            #pragma unroll
            for (int i = 0; i < C_; ++i) s = fmaf(bp[i], wn[i], s);
            sm[OFF_SY + idx] = s;
        }
        float ws[C_];
        #pragma unroll
        for (int i = 0; i < C_; ++i) ws[i] = sm[OFF_WSELF + i * HID_ + j];
        const float bs = sm[OFF_BASE + j];
        for (int idx = tid; idx < NPIX * HID_; idx += NTHREADS) {
            int p = idx >> 6;
            int r = p >> 5, c = p & 31;
            const float* bp = &sm[OFF_SB + ((r + 1) * HW + (c + 1)) * C_];
            float s = bs;
            #pragma unroll
            for (int i = 0; i < C_; ++i) s = fmaf(bp[i], ws[i], s);
            sm[OFF_SA + idx] = s;
        }
    }
    __syncthreads();

    // ---------------- Phase 3: per-pixel message+update+LN ----------------
    // 8 lanes per pixel, each lane owns 8 hidden units. 4 pixels per warp.
    const int wid  = tid >> 5;
    const int lane = tid & 31;
    const int g    = lane >> 3;   // pixel group within warp
    const int li   = lane & 7;    // lane within group
    const int j0   = li << 3;     // hidden base

    const int DY[8] = {-1,-1,-1, 0, 0, 1, 1, 1};
    const int DX[8] = {-1, 0, 1,-1, 1,-1, 0, 1};

    float wc[3][8];
    #pragma unroll
    for (int k = 0; k < 3; ++k) {
        *(float4*)&wc[k][0] = *(const float4*)&sm[OFF_WC + k * 64 + j0];
        *(float4*)&wc[k][4] = *(const float4*)&sm[OFF_WC + k * 64 + j0 + 4];
    }

    #pragma unroll 1
    for (int pass = 0; pass < 4; ++pass) {
        const int p  = pass * 64 + wid * 4 + g;
        const int r  = p >> 5, c = p & 31;
        const int hp = (r + 1) * HW + (c + 1);

        float a[8];
        *(float4*)&a[0] = *(const float4*)&sm[OFF_SA + p * 64 + j0];
        *(float4*)&a[4] = *(const float4*)&sm[OFF_SA + p * 64 + j0 + 4];
        float hs[8] = {0.f,0.f,0.f,0.f,0.f,0.f,0.f,0.f};
        const float* cp = &sm[OFF_SC + p * 24];

        #pragma unroll
        for (int d = 0; d < 8; ++d) {
            const int np = hp + DY[d] * HW + DX[d];
            float yn[8];
            *(float4*)&yn[0] = *(const float4*)&sm[OFF_SY + np * 64 + j0];
            *(float4*)&yn[4] = *(const float4*)&sm[OFF_SY + np * 64 + j0 + 4];
            const float c0 = cp[3*d], c1 = cp[3*d+1], c2 = cp[3*d+2];
            #pragma unroll
            for (int jj = 0; jj < 8; ++jj) {
                float t = fmaf(c0, wc[0][jj], a[jj] + yn[jj]);
                t = fmaf(c1, wc[1][jj], t);
                t = fmaf(c2, wc[2][jj], t);
                hs[jj] += fmaxf(t, 0.f);
            }
        }

        // agg = (mean_d relu(h))@mw2 + mb2 ; partial per lane, reduce over 8 lanes
        float agg[10];
        #pragma unroll
        for (int k = 0; k < 10; ++k) {
            float s = 0.f;
            #pragma unroll
            for (int jj = 0; jj < 8; ++jj)
                s = fmaf(hs[jj], sm[OFF_MW2T + k * 64 + j0 + jj], s);
            agg[k] = s;
        }
        #pragma unroll
        for (int o = 1; o < 8; o <<= 1) {
            #pragma unroll
            for (int k = 0; k < 10; ++k)
                agg[k] += __shfl_xor_sync(0xffffffffu, agg[k], o);
        }
        #pragma unroll
        for (int k = 0; k < 10; ++k)
            agg[k] = fmaf(agg[k], 0.125f, sm[OFF_MB2 + k]);

        // update net
        float sf[10];
        #pragma unroll
        for (int i = 0; i < 10; ++i) sf[i] = sm[OFF_SB + hp * C_ + i];

        float u[8];
        *(float4*)&u[0] = *(const float4*)&sm[OFF_UB1 + j0];
        *(float4*)&u[4] = *(const float4*)&sm[OFF_UB1 + j0 + 4];
        #pragma unroll
        for (int i = 0; i < 20; ++i) {
            const float v = (i < 10) ? sf[i] : agg[i - 10];
            const float4* wr = (const float4*)&sm[OFF_UW1 + i * 64 + j0];
            const float4 wa = wr[0], wb = wr[1];
            u[0] = fmaf(v, wa.x, u[0]); u[1] = fmaf(v, wa.y, u[1]);
            u[2] = fmaf(v, wa.z, u[2]); u[3] = fmaf(v, wa.w, u[3]);
            u[4] = fmaf(v, wb.x, u[4]); u[5] = fmaf(v, wb.y, u[5]);
            u[6] = fmaf(v, wb.z, u[6]); u[7] = fmaf(v, wb.w, u[7]);
        }
        #pragma unroll
        for (int jj = 0; jj < 8; ++jj) u[jj] = fmaxf(u[jj], 0.f);

        float upd[10];
        #pragma unroll
        for (int k = 0; k < 10; ++k) {
            float s = 0.f;
            #pragma unroll
            for (int jj = 0; jj < 8; ++jj)
                s = fmaf(u[jj], sm[OFF_UW2T + k * 64 + j0 + jj], s);
            upd[k] = s;
        }
        #pragma unroll
        for (int o = 1; o < 8; o <<= 1) {
            #pragma unroll
            for (int k = 0; k < 10; ++k)
                upd[k] += __shfl_xor_sync(0xffffffffu, upd[k], o);
        }

        // residual + layernorm
        float x[10]; float mu = 0.f;
        #pragma unroll
        for (int k = 0; k < 10; ++k) {
            float xv = fmaf(0.5f, upd[k] + sm[OFF_UB2 + k], sf[k]);
            x[k] = xv; mu += xv;
        }
        mu *= 0.1f;
        float var = 0.f;
        #pragma unroll
        for (int k = 0; k < 10; ++k) { float dk = x[k] - mu; var = fmaf(dk, dk, var); }
        const float inv = rsqrtf(var * 0.1f + 1e-5f);
        #pragma unroll
        for (int k = 0; k < 10; ++k)
            x[k] = fmaf((x[k] - mu) * inv, sm[OFF_GAMMA + k], sm[OFF_BETA + k]);

        if (li == 0) {
            #pragma unroll
            for (int k = 0; k < 10; k += 2) {
                float2 v; v.x = x[k]; v.y = x[k + 1];
                *(float2*)&sm[OFF_SOUT + p * C_ + k] = v;
            }
        }
    }
    __syncthreads();

    // ---------------- Phase 4: coalesced float4 store ----------------
    {
        const float4* src = (const float4*)&sm[OFF_SOUT];
        for (int idx = tid; idx < NPIX * C_ / 4; idx += NTHREADS) {
            int r = idx / 80, o = idx - r * 80;
            float4* dst = (float4*)(out + ((size_t)(b * H_ + y0 + r) * W_ + x0) * C_);
            dst[o] = src[idx];
        }
    }
}

extern "C" void kernel_launch(void* const* d_in, const int* in_sizes, int n_in,
                              void* d_out, int out_size)
{
    const float* beliefs     = (const float*)d_in[0];
    const float* constraints = (const float*)d_in[1];
    const float* fnembed     = (const float*)d_in[2];
    const float* mw1         = (const float*)d_in[3];
    const float* mb1         = (const float*)d_in[4];
    const float* mw2         = (const float*)d_in[5];
    const float* mb2         = (const float*)d_in[6];
    const float* uw1         = (const float*)d_in[7];
    const float* ub1         = (const float*)d_in[8];
    const float* uw2         = (const float*)d_in[9];
    const float* ub2         = (const float*)d_in[10];
    const float* gamma_      = (const float*)d_in[11];
    const float* beta_       = (const float*)d_in[12];
    float* out = (float*)d_out;

    cudaFuncSetAttribute(cmp_kernel, cudaFuncAttributeMaxDynamicSharedMemorySize, SMEM_BYTES);

    dim3 grid(W_ / TW, H_ / TH, B_);
    cmp_kernel<<<grid, NTHREADS, SMEM_BYTES>>>(
        beliefs, constraints, fnembed, mw1, mb1, mw2, mb2,
        uw1, ub1, uw2, ub2, gamma_, beta_, out);
}

// round 4
// speedup vs baseline: 1.4313x; 1.4313x over previous
#include <cuda_runtime.h>
#include <cstdint>

// Problem constants
#define B_  64
#define H_  128
#define W_  128
#define C_  10
#define FD_ 32
#define HID_ 64

// Tile config
#define TW 32
#define TH 8
#define HW 34   // halo width  (TW+2)
#define HH 10   // halo height (TH+2)
#define NPIX  (TW*TH)   // 256
#define NHALO (HW*HH)   // 340
#define NTHREADS 512

// Shared memory layout (float offsets). Regions are reused across phases:
//   SOUT aliases SY  (SY dead after phase C)
//   SAGG aliases SC  (SC dead after phase C)
//   SU   aliases SHS (SHS dead after phase D)
#define OFF_SY     0                          // NHALO*64 = 21760
#define OFF_SOUT   OFF_SY                     // NPIX*10  = 2560 (phase F/G)
#define OFF_SB     (OFF_SY + NHALO*HID_)      // 21760 ; rows padded to 12
#define OFF_SC     (OFF_SB + NHALO*12)        // 25840 ; NPIX*24 = 6144
#define OFF_SAGG   OFF_SC                     // NPIX*12 = 3072 (phase D/E)
#define OFF_SHS    (OFF_SC + NPIX*24)         // 31984 ; NPIX*64 = 16384
#define OFF_SU     OFF_SHS                    // NPIX*64 (phase E/F)
#define OFF_WSELF  (OFF_SHS + NPIX*HID_)      // 48368
#define OFF_WNEIGH (OFF_WSELF + 640)
#define OFF_WC     (OFF_WNEIGH + 640)
#define OFF_MW2T   (OFF_WC + 192)
#define OFF_UW2T   (OFF_MW2T + 640)
#define OFF_UW1    (OFF_UW2T + 640)
#define OFF_UB1    (OFF_UW1 + 1280)
#define OFF_BASE   (OFF_UB1 + 64)
#define OFF_MB2    (OFF_BASE + 64)
#define OFF_UB2    (OFF_MB2 + 12)
#define OFF_GAMMA  (OFF_UB2 + 12)
#define OFF_BETA   (OFF_GAMMA + 12)
#define SMEM_FLOATS (OFF_BETA + 12)           // 52624
#define SMEM_BYTES  (SMEM_FLOATS * 4)         // 210496

__global__ void __launch_bounds__(NTHREADS, 1)
cmp_kernel(const float* __restrict__ beliefs,
           const float* __restrict__ constraints,
           const float* __restrict__ fnembed,
           const float* __restrict__ mw1, const float* __restrict__ mb1,
           const float* __restrict__ mw2, const float* __restrict__ mb2,
           const float* __restrict__ uw1, const float* __restrict__ ub1,
           const float* __restrict__ uw2, const float* __restrict__ ub2,
           const float* __restrict__ gamma_, const float* __restrict__ beta_,
           float* __restrict__ out)
{
    extern __shared__ __align__(16) float sm[];
    const int tid = threadIdx.x;
    const int b  = blockIdx.z;
    const int x0 = blockIdx.x * TW;
    const int y0 = blockIdx.y * TH;

    // ================= Phase A: stage weights + inputs into smem =================
    // mw1 row layout: rows [0,10)=W_self, [10,20)=W_neigh, [20,23)=W_con, [23,55)=W_fn
    for (int i = tid; i < 640; i += NTHREADS) {
        sm[OFF_WSELF  + i] = mw1[i];
        sm[OFF_WNEIGH + i] = mw1[640 + i];
        sm[OFF_MW2T + i] = mw2[(i & 63) * 10 + (i >> 6)];   // [k][j]
        sm[OFF_UW2T + i] = uw2[(i & 63) * 10 + (i >> 6)];
    }
    for (int i = tid; i < 192; i += NTHREADS)  sm[OFF_WC  + i] = mw1[1280 + i];
    for (int i = tid; i < 1280; i += NTHREADS) sm[OFF_UW1 + i] = uw1[i];
    if (tid < 64) {
        sm[OFF_UB1 + tid] = ub1[tid];
        float s = mb1[tid];
        const float* f = fnembed + b * FD_;
        #pragma unroll
        for (int k = 0; k < FD_; ++k)
            s = fmaf(f[k], mw1[(23 + k) * HID_ + tid], s);
        sm[OFF_BASE + tid] = s;
    }
    if (tid >= 64 && tid < 74) {
        int k = tid - 64;
        sm[OFF_MB2   + k] = mb2[k];
        sm[OFF_UB2   + k] = ub2[k];
        sm[OFF_GAMMA + k] = gamma_[k];
        sm[OFF_BETA  + k] = beta_[k];
    }

    // beliefs halo (replicate-pad), rows padded to 12 floats
    for (int idx = tid; idx < NHALO * C_; idx += NTHREADS) {
        int p = idx / C_, i = idx - p * C_;
        int hr = p / HW, hc = p - hr * HW;
        int gy = min(max(y0 - 1 + hr, 0), H_ - 1);
        int gx = min(max(x0 - 1 + hc, 0), W_ - 1);
        sm[OFF_SB + p * 12 + i] = beliefs[((size_t)(b * H_ + gy) * W_ + gx) * C_ + i];
    }
    // constraints tile (float4, coalesced)
    {
        float4* dst = (float4*)&sm[OFF_SC];
        for (int idx = tid; idx < NPIX * 6; idx += NTHREADS) {
            int r = idx / (TW * 6), o = idx - r * (TW * 6);
            const float4* src = (const float4*)(constraints +
                ((size_t)(b * H_ + y0 + r) * W_ + x0) * 24);
            dst[idx] = src[o];
        }
    }
    __syncthreads();

    const int j   = tid & 63;
    const int rep = tid >> 6;   // 0..7

    // ================= Phase B: y = beliefs @ W_neigh over halo =================
    {
        float wn[C_];
        #pragma unroll
        for (int i = 0; i < C_; ++i) wn[i] = sm[OFF_WNEIGH + i * HID_ + j];
        for (int hp = rep; hp < NHALO; hp += 8) {
            const float4 s0 = *(const float4*)&sm[OFF_SB + hp * 12];
            const float4 s1 = *(const float4*)&sm[OFF_SB + hp * 12 + 4];
            const float2 s2 = *(const float2*)&sm[OFF_SB + hp * 12 + 8];
            float y = 0.f;
            y = fmaf(s0.x, wn[0], y); y = fmaf(s0.y, wn[1], y);
            y = fmaf(s0.z, wn[2], y); y = fmaf(s0.w, wn[3], y);
            y = fmaf(s1.x, wn[4], y); y = fmaf(s1.y, wn[5], y);
            y = fmaf(s1.z, wn[6], y); y = fmaf(s1.w, wn[7], y);
            y = fmaf(s2.x, wn[8], y); y = fmaf(s2.y, wn[9], y);
            sm[OFF_SY + hp * HID_ + j] = y;
        }
    }
    __syncthreads();

    // ================= Phase C: hs(p,j) = sum_d relu(a + y_nb + c@wc) =================
    {
        float ws[C_];
        #pragma unroll
        for (int i = 0; i < C_; ++i) ws[i] = sm[OFF_WSELF + i * HID_ + j];
        const float wc0 = sm[OFF_WC + j];
        const float wc1 = sm[OFF_WC + 64 + j];
        const float wc2 = sm[OFF_WC + 128 + j];
        const float bs  = sm[OFF_BASE + j];

        const int row = rep;                 // 0..7
        const int rt = row * HW, rm = (row + 1) * HW, rb = (row + 2) * HW;

        // sliding 3x3 y-window (center unused but carried)
        float yw[9];
        yw[0] = sm[OFF_SY + (rt + 0) * HID_ + j];
        yw[1] = sm[OFF_SY + (rt + 1) * HID_ + j];
        yw[3] = sm[OFF_SY + (rm + 0) * HID_ + j];
        yw[4] = sm[OFF_SY + (rm + 1) * HID_ + j];
        yw[6] = sm[OFF_SY + (rb + 0) * HID_ + j];
        yw[7] = sm[OFF_SY + (rb + 1) * HID_ + j];

        #pragma unroll 1
        for (int x = 0; x < TW; ++x) {
            yw[2] = sm[OFF_SY + (rt + x + 2) * HID_ + j];
            yw[5] = sm[OFF_SY + (rm + x + 2) * HID_ + j];
            yw[8] = sm[OFF_SY + (rb + x + 2) * HID_ + j];

            const int p   = row * TW + x;
            const int hpc = rm + x + 1;

            // a = base + self @ W_self  (uniform vec loads)
            const float4 s0 = *(const float4*)&sm[OFF_SB + hpc * 12];
            const float4 s1 = *(const float4*)&sm[OFF_SB + hpc * 12 + 4];
            const float2 s2 = *(const float2*)&sm[OFF_SB + hpc * 12 + 8];
            float a = bs;
            a = fmaf(s0.x, ws[0], a); a = fmaf(s0.y, ws[1], a);
            a = fmaf(s0.z, ws[2], a); a = fmaf(s0.w, ws[3], a);
            a = fmaf(s1.x, ws[4], a); a = fmaf(s1.y, ws[5], a);
            a = fmaf(s1.z, ws[6], a); a = fmaf(s1.w, ws[7], a);
            a = fmaf(s2.x, ws[8], a); a = fmaf(s2.y, ws[9], a);

            // constraints (uniform vec loads -> regs)
            float cc[24];
            #pragma unroll
            for (int q = 0; q < 6; ++q) {
                const float4 v = *(const float4*)&sm[OFF_SC + p * 24 + q * 4];
                cc[q*4+0] = v.x; cc[q*4+1] = v.y; cc[q*4+2] = v.z; cc[q*4+3] = v.w;
            }

            const int DI[8] = {0,1,2,3,5,6,7,8};
            float hs = 0.f;
            #pragma unroll
            for (int d = 0; d < 8; ++d) {
                float t = a + yw[DI[d]];
                t = fmaf(cc[3*d+0], wc0, t);
                t = fmaf(cc[3*d+1], wc1, t);
                t = fmaf(cc[3*d+2], wc2, t);
                hs += fmaxf(t, 0.f);
            }
            sm[OFF_SHS + p * HID_ + j] = hs;

            yw[0]=yw[1]; yw[1]=yw[2];
            yw[3]=yw[4]; yw[4]=yw[5];
            yw[6]=yw[7]; yw[7]=yw[8];
        }
    }
    __syncthreads();

    // 8-lane-group mapping for phases D and F
    const int wid  = tid >> 5;
    const int lane = tid & 31;
    const int g    = lane >> 3;
    const int li   = lane & 7;
    const int j0   = li << 3;

    // ================= Phase D: agg = (mean_d relu)@mw2 + mb2 =================
    {
        float w2[10][8];   // register-resident across all passes
        #pragma unroll
        for (int k = 0; k < 10; ++k) {
            *(float4*)&w2[k][0] = *(const float4*)&sm[OFF_MW2T + k * 64 + j0];
            *(float4*)&w2[k][4] = *(const float4*)&sm[OFF_MW2T + k * 64 + j0 + 4];
        }
        float mb2r[10];
        #pragma unroll
        for (int k = 0; k < 10; ++k) mb2r[k] = sm[OFF_MB2 + k];

        #pragma unroll 1
        for (int pass = 0; pass < 4; ++pass) {
            const int p = pass * 64 + wid * 4 + g;
            float hs[8];
            *(float4*)&hs[0] = *(const float4*)&sm[OFF_SHS + p * 64 + j0];
            *(float4*)&hs[4] = *(const float4*)&sm[OFF_SHS + p * 64 + j0 + 4];
            float agg[10];
            #pragma unroll
            for (int k = 0; k < 10; ++k) {
                float s = 0.f;
                #pragma unroll
                for (int jj = 0; jj < 8; ++jj) s = fmaf(hs[jj], w2[k][jj], s);
                agg[k] = s;
            }
            #pragma unroll
            for (int o = 1; o < 8; o <<= 1) {
                #pragma unroll
                for (int k = 0; k < 10; ++k)
                    agg[k] += __shfl_xor_sync(0xffffffffu, agg[k], o);
            }
            if (li == 0) {
                #pragma unroll
                for (int k = 0; k < 10; k += 2) {
                    float2 v; v.x = fmaf(agg[k],   0.125f, mb2r[k]);
                              v.y = fmaf(agg[k+1], 0.125f, mb2r[k+1]);
                    *(float2*)&sm[OFF_SAGG + p * 12 + k] = v;
                }
            }
        }
    }
    __syncthreads();

    // ================= Phase E: u = relu([self,agg] @ uw1 + ub1) =================
    {
        float w1[20];      // uw1[:, j] register-resident
        #pragma unroll
        for (int i = 0; i < 20; ++i) w1[i] = sm[OFF_UW1 + i * 64 + j];
        const float b1 = sm[OFF_UB1 + j];

        #pragma unroll 1
        for (int t = 0; t < 32; ++t) {
            const int p = rep * 32 + t;
            const int hpc = ((p >> 5) + 1) * HW + (p & 31) + 1;
            const float4 s0 = *(const float4*)&sm[OFF_SB + hpc * 12];
            const float4 s1 = *(const float4*)&sm[OFF_SB + hpc * 12 + 4];
            const float2 s2 = *(const float2*)&sm[OFF_SB + hpc * 12 + 8];
            const float4 a0 = *(const float4*)&sm[OFF_SAGG + p * 12];
            const float4 a1 = *(const float4*)&sm[OFF_SAGG + p * 12 + 4];
            const float2 a2 = *(const float2*)&sm[OFF_SAGG + p * 12 + 8];
            float u = b1;
            u = fmaf(s0.x, w1[0], u);  u = fmaf(s0.y, w1[1], u);
            u = fmaf(s0.z, w1[2], u);  u = fmaf(s0.w, w1[3], u);
            u = fmaf(s1.x, w1[4], u);  u = fmaf(s1.y, w1[5], u);
            u = fmaf(s1.z, w1[6], u);  u = fmaf(s1.w, w1[7], u);
            u = fmaf(s2.x, w1[8], u);  u = fmaf(s2.y, w1[9], u);
            u = fmaf(a0.x, w1[10], u); u = fmaf(a0.y, w1[11], u);
            u = fmaf(a0.z, w1[12], u); u = fmaf(a0.w, w1[13], u);
            u = fmaf(a1.x, w1[14], u); u = fmaf(a1.y, w1[15], u);
            u = fmaf(a1.z, w1[16], u); u = fmaf(a1.w, w1[17], u);
            u = fmaf(a2.x, w1[18], u); u = fmaf(a2.y, w1[19], u);
            sm[OFF_SU + p * 64 + j] = fmaxf(u, 0.f);
        }
    }
    __syncthreads();

    // ================= Phase F: upd = u @ uw2 + ub2 ; residual + LN =================
    {
        float w2[10][8];   // uw2t register-resident
        #pragma unroll
        for (int k = 0; k < 10; ++k) {
            *(float4*)&w2[k][0] = *(const float4*)&sm[OFF_UW2T + k * 64 + j0];
            *(float4*)&w2[k][4] = *(const float4*)&sm[OFF_UW2T + k * 64 + j0 + 4];
        }
        float ub2r[10], gr[10], br[10];
        #pragma unroll
        for (int k = 0; k < 10; ++k) {
            ub2r[k] = sm[OFF_UB2 + k];
            gr[k]   = sm[OFF_GAMMA + k];
            br[k]   = sm[OFF_BETA + k];
        }

        #pragma unroll 1
        for (int pass = 0; pass < 4; ++pass) {
            const int p = pass * 64 + wid * 4 + g;
            float u[8];
            *(float4*)&u[0] = *(const float4*)&sm[OFF_SU + p * 64 + j0];
            *(float4*)&u[4] = *(const float4*)&sm[OFF_SU + p * 64 + j0 + 4];
            float upd[10];
            #pragma unroll
            for (int k = 0; k < 10; ++k) {
                float s = 0.f;
                #pragma unroll
                for (int jj = 0; jj < 8; ++jj) s = fmaf(u[jj], w2[k][jj], s);
                upd[k] = s;
            }
            #pragma unroll
            for (int o = 1; o < 8; o <<= 1) {
                #pragma unroll
                for (int k = 0; k < 10; ++k)
                    upd[k] += __shfl_xor_sync(0xffffffffu, upd[k], o);
            }
            if (li == 0) {
                const int hpc = ((p >> 5) + 1) * HW + (p & 31) + 1;
                const float4 s0 = *(const float4*)&sm[OFF_SB + hpc * 12];
                const float4 s1 = *(const float4*)&sm[OFF_SB + hpc * 12 + 4];
                const float2 s2 = *(const float2*)&sm[OFF_SB + hpc * 12 + 8];
                float sf[10] = {s0.x,s0.y,s0.z,s0.w,s1.x,s1.y,s1.z,s1.w,s2.x,s2.y};
                float x[10]; float mu = 0.f;
                #pragma unroll
                for (int k = 0; k < 10; ++k) {
                    float xv = fmaf(0.5f, upd[k] + ub2r[k], sf[k]);
                    x[k] = xv; mu += xv;
                }
                mu *= 0.1f;
                float var = 0.f;
                #pragma unroll
                for (int k = 0; k < 10; ++k) { float dk = x[k] - mu; var = fmaf(dk, dk, var); }
                const float inv = rsqrtf(var * 0.1f + 1e-5f);
                #pragma unroll
                for (int k = 0; k < 10; k += 2) {
                    float2 v;
                    v.x = fmaf((x[k]   - mu) * inv, gr[k],   br[k]);
                    v.y = fmaf((x[k+1] - mu) * inv, gr[k+1], br[k+1]);
                    *(float2*)&sm[OFF_SOUT + p * C_ + k] = v;
                }
            }
        }
    }
    __syncthreads();

    // ================= Phase G: coalesced float4 store =================
    {
        const float4* src = (const float4*)&sm[OFF_SOUT];
        for (int idx = tid; idx < NPIX * C_ / 4; idx += NTHREADS) {
            int r = idx / 80, o = idx - r * 80;
            float4* dst = (float4*)(out + ((size_t)(b * H_ + y0 + r) * W_ + x0) * C_);
            dst[o] = src[idx];
        }
    }
}

extern "C" void kernel_launch(void* const* d_in, const int* in_sizes, int n_in,
                              void* d_out, int out_size)
{
    const float* beliefs     = (const float*)d_in[0];
    const float* constraints = (const float*)d_in[1];
    const float* fnembed     = (const float*)d_in[2];
    const float* mw1         = (const float*)d_in[3];
    const float* mb1         = (const float*)d_in[4];
    const float* mw2         = (const float*)d_in[5];
    const float* mb2         = (const float*)d_in[6];
    const float* uw1         = (const float*)d_in[7];
    const float* ub1         = (const float*)d_in[8];
    const float* uw2         = (const float*)d_in[9];
    const float* ub2         = (const float*)d_in[10];
    const float* gamma_      = (const float*)d_in[11];
    const float* beta_       = (const float*)d_in[12];
    float* out = (float*)d_out;

    cudaFuncSetAttribute(cmp_kernel, cudaFuncAttributeMaxDynamicSharedMemorySize, SMEM_BYTES);

    dim3 grid(W_ / TW, H_ / TH, B_);
    cmp_kernel<<<grid, NTHREADS, SMEM_BYTES>>>(
        beliefs, constraints, fnembed, mw1, mb1, mw2, mb2,
        uw1, ub1, uw2, ub2, gamma_, beta_, out);
}